// round 17
// baseline (speedup 1.0000x reference)
#include <cuda_runtime.h>
#include <cuda_bf16.h>
#include <cstdint>

#define MAXN 50000
#define MAXE 800000
#define H 64
#define HC 16   // H/4 float4 chunks
#define EPS 1e-5f

// ------------------------- device scratch (no allocs allowed) -------------------------
// Zero-state invariant: g_degcnt, g_pool, g_sum, g_sumsq, barrier counters are zero at
// entry of every kernel_launch call (zero at load; each replay restores them).
__device__ __align__(256) float g_bufA[MAXN * H];   // layer output y (agg result)
__device__ __align__(256) float g_bufB[MAXN * H];   // hs = (act @ W^T) * dinv
__device__ int   g_degcnt[MAXN];
__device__ int   g_rowptr[MAXN + 1];
__device__ int   g_cursor[MAXN];
__device__ int   g_csrsrc[MAXE];
__device__ float g_dinv[MAXN];
__device__ float g_sum[3 * H];     // per-layer BN stats
__device__ float g_sumsq[3 * H];
__device__ float g_pool[64 * H];
__device__ int   g_bsum[64];
__device__ volatile int g_bar1, g_bar2;   // CSR-build software barriers (one-shot)
__device__ int   g_barexit;               // exit counter (resets barriers)
__device__ int   g_pooldone;              // pool last-block counter

// ------------------------- CSR build: hist + scan + dinv in ONE kernel --------------------
// 49 blocks x 1024 threads (trivially co-resident on 148 SMs -> software barriers safe).
// Phase1: histogram. Barrier. Phase2: per-block inclusive scan of its 1024-chunk.
// Barrier. Phase3: add block offsets, write rowptr/cursor/dinv, restore zeros.
__device__ __forceinline__ int block_incl_scan(int v, int tid) {
    __shared__ int ws[32];
    int lane = tid & 31, w = tid >> 5;
    #pragma unroll
    for (int o = 1; o < 32; o <<= 1) {
        int t = __shfl_up_sync(0xffffffffu, v, o);
        if (lane >= o) v += t;
    }
    if (lane == 31) ws[w] = v;
    __syncthreads();
    if (w == 0) {
        int s = ws[lane];
        #pragma unroll
        for (int o = 1; o < 32; o <<= 1) {
            int t = __shfl_up_sync(0xffffffffu, s, o);
            if (lane >= o) s += t;
        }
        ws[lane] = s;
    }
    __syncthreads();
    return v + (w > 0 ? ws[w - 1] : 0);
}

__device__ __forceinline__ void grid_barrier(volatile int* bar, int nblocks, int tid) {
    __syncthreads();
    __threadfence();
    if (tid == 0) atomicAdd((int*)bar, 1);
    if (tid == 0) { while (*bar < nblocks) { } }
    __syncthreads();
    __threadfence();
}

__global__ void __launch_bounds__(1024) csr_build_kernel(const int* __restrict__ ei,
                                                         int n, int e) {
    int tid = threadIdx.x;
    int nb = gridDim.x;

    // Phase 1: degree histogram (grid-stride over edges)
    {
        int i = blockIdx.x * 1024 + tid;
        int stride = nb * 1024;
        for (int t = i; t < e; t += stride) {
            int dst = ei[e + t];
            atomicAdd(&g_degcnt[dst], 1);
        }
    }
    grid_barrier(&g_bar1, nb, tid);

    // Phase 2: per-block scan
    int gid = blockIdx.x * 1024 + tid;
    int v = (gid < n) ? g_degcnt[gid] : 0;
    int incl = block_incl_scan(v, tid);
    if (gid < n) g_rowptr[gid] = incl - v;   // exclusive within block
    if (tid == 1023) g_bsum[blockIdx.x] = incl;
    grid_barrier(&g_bar2, nb, tid);

    // Phase 3: block offset (sum of g_bsum[0..bid-1], <=64 values) + outputs
    __shared__ int part[2];
    __shared__ int s_off;
    if (tid < 64) {
        int pv = (tid < blockIdx.x && tid < nb) ? g_bsum[tid] : 0;
        #pragma unroll
        for (int o = 16; o; o >>= 1) pv += __shfl_xor_sync(0xffffffffu, pv, o);
        if ((tid & 31) == 0) part[tid >> 5] = pv;
    }
    __syncthreads();
    if (tid == 0) s_off = part[0] + part[1];
    __syncthreads();
    int off = s_off;

    if (gid < n) {
        int d = g_degcnt[gid];
        int r = (incl - v) + off;
        g_rowptr[gid] = r;
        g_cursor[gid] = r;
        g_dinv[gid] = rsqrtf((float)d + 1.0f);
        g_degcnt[gid] = 0;                   // restore zero invariant
    }
    if (gid == 0) g_rowptr[n] = e;

    // last block to exit resets the barrier counters (all blocks passed both)
    __syncthreads();
    if (tid == 0) {
        int ex = atomicAdd(&g_barexit, 1);
        if (ex == nb - 1) {
            g_bar1 = 0;
            g_bar2 = 0;
            g_barexit = 0;
        }
    }
}

// ------------------------- tf32 MMA helpers -------------------------
__device__ __forceinline__ unsigned f2tf32(float f) {
    unsigned r;
    asm("cvt.rna.tf32.f32 %0, %1;" : "=r"(r) : "f"(f));
    return r;
}
__device__ __forceinline__ void mma_tf32(float c[4], unsigned a0, unsigned a1,
                                         unsigned a2, unsigned a3,
                                         unsigned b0, unsigned b1) {
    asm volatile(
        "mma.sync.aligned.m16n8k8.row.col.f32.tf32.tf32.f32 "
        "{%0,%1,%2,%3}, {%4,%5,%6,%7}, {%8,%9}, {%0,%1,%2,%3};"
        : "+f"(c[0]), "+f"(c[1]), "+f"(c[2]), "+f"(c[3])
        : "r"(a0), "r"(a1), "r"(a2), "r"(a3), "r"(b0), "r"(b1));
}

// ------------------------- GEMM body (tensor core, reg-prefetch pipelined) -----------------
#define KT 16
#define AST 136
template <int K, bool BN, bool FROMX>
__device__ __forceinline__ void gemm_body(const float* __restrict__ in,
                                          const float* __restrict__ W,
                                          const float* __restrict__ gamma,
                                          const float* __restrict__ beta,
                                          int n, int layer, float fn, int blk) {
    constexpr int WST = K + 4;
    __shared__ unsigned a_sm[KT * AST];
    __shared__ unsigned w_sm[64 * WST];
    __shared__ float sScale[H], sShift[H];

    int tid = threadIdx.x;
    int row0 = blk * 128;

    if (BN && tid < H) {
        float m = g_sum[layer * H + tid] / fn;
        float var = g_sumsq[layer * H + tid] / fn - m * m;
        float inv = rsqrtf(var + EPS);
        float sc = inv * gamma[tid];
        sScale[tid] = sc;
        sShift[tid] = beta[tid] - m * sc;
    }
    #pragma unroll
    for (int it = 0; it < K / 16; it++) {
        int idx = it * 256 + tid;
        int o = idx / (K / 4);
        int kc = (idx % (K / 4)) << 2;
        float4 wv = *(const float4*)&W[o * K + kc];
        uint4 u;
        u.x = f2tf32(wv.x); u.y = f2tf32(wv.y);
        u.z = f2tf32(wv.z); u.w = f2tf32(wv.w);
        *(uint4*)&w_sm[o * WST + kc] = u;
    }

    const float* src = FROMX ? in : g_bufA;

    int lane = tid & 31, warp = tid >> 5;
    int g = lane >> 2, t = lane & 3;
    int wm = warp & 3, wn = warp >> 2;
    int r0 = wm * 32;
    int c0 = wn * 32;

    int rowA[2], kcA[2], rgA[2];
    #pragma unroll
    for (int it = 0; it < 2; it++) {
        int idx = it * 256 + tid;
        rowA[it] = idx & 127;
        kcA[it] = (idx >> 7) << 2;
        rgA[it] = row0 + rowA[it];
    }

    float c[2][4][4];
    #pragma unroll
    for (int m = 0; m < 2; m++)
        #pragma unroll
        for (int nb = 0; nb < 4; nb++)
            #pragma unroll
            for (int i = 0; i < 4; i++) c[m][nb][i] = 0.f;

    float4 pf[2];
    #pragma unroll
    for (int it = 0; it < 2; it++)
        pf[it] = (rgA[it] < n) ? *(const float4*)&src[(size_t)rgA[it] * K + kcA[it]]
                               : make_float4(0.f, 0.f, 0.f, 0.f);
    __syncthreads();

    #pragma unroll
    for (int kt = 0; kt < K; kt += KT) {
        #pragma unroll
        for (int it = 0; it < 2; it++) {
            float4 av = pf[it];
            int kc = kcA[it];
            if (BN) {
                float4 sc4 = *(const float4*)&sScale[kt + kc];
                float4 sh4 = *(const float4*)&sShift[kt + kc];
                av.x = fmaxf(fmaf(av.x, sc4.x, sh4.x), 0.f);
                av.y = fmaxf(fmaf(av.y, sc4.y, sh4.y), 0.f);
                av.z = fmaxf(fmaf(av.z, sc4.z, sh4.z), 0.f);
                av.w = fmaxf(fmaf(av.w, sc4.w, sh4.w), 0.f);
            }
            a_sm[(kc + 0) * AST + rowA[it]] = f2tf32(av.x);
            a_sm[(kc + 1) * AST + rowA[it]] = f2tf32(av.y);
            a_sm[(kc + 2) * AST + rowA[it]] = f2tf32(av.z);
            a_sm[(kc + 3) * AST + rowA[it]] = f2tf32(av.w);
        }
        __syncthreads();

        if (kt + KT < K) {
            #pragma unroll
            for (int it = 0; it < 2; it++)
                pf[it] = (rgA[it] < n)
                    ? *(const float4*)&src[(size_t)rgA[it] * K + kt + KT + kcA[it]]
                    : make_float4(0.f, 0.f, 0.f, 0.f);
        }

        #pragma unroll
        for (int ks = 0; ks < KT; ks += 8) {
            unsigned a[2][4];
            #pragma unroll
            for (int m = 0; m < 2; m++) {
                int rb = r0 + m * 16;
                a[m][0] = a_sm[(ks + t) * AST + rb + g];
                a[m][1] = a_sm[(ks + t) * AST + rb + g + 8];
                a[m][2] = a_sm[(ks + t + 4) * AST + rb + g];
                a[m][3] = a_sm[(ks + t + 4) * AST + rb + g + 8];
            }
            #pragma unroll
            for (int nb = 0; nb < 4; nb++) {
                int o = c0 + nb * 8 + g;
                unsigned b0 = w_sm[o * WST + kt + ks + t];
                unsigned b1 = w_sm[o * WST + kt + ks + t + 4];
                mma_tf32(c[0][nb], a[0][0], a[0][1], a[0][2], a[0][3], b0, b1);
                mma_tf32(c[1][nb], a[1][0], a[1][1], a[1][2], a[1][3], b0, b1);
            }
        }
        __syncthreads();
    }

    #pragma unroll
    for (int m = 0; m < 2; m++) {
        int rA = row0 + r0 + m * 16 + g;
        int rB = rA + 8;
        float dvA = (rA < n) ? g_dinv[rA] : 0.f;
        float dvB = (rB < n) ? g_dinv[rB] : 0.f;
        #pragma unroll
        for (int nb = 0; nb < 4; nb++) {
            int col = c0 + nb * 8 + 2 * t;
            if (rA < n) {
                float2 v = make_float2(c[m][nb][0] * dvA, c[m][nb][1] * dvA);
                *(float2*)&g_bufB[(size_t)rA * H + col] = v;
            }
            if (rB < n) {
                float2 v = make_float2(c[m][nb][2] * dvB, c[m][nb][3] * dvB);
                *(float2*)&g_bufB[(size_t)rB * H + col] = v;
            }
        }
    }
}

// Fused layer-0 kernel: first gemmBlocks blocks do the K=128 GEMM; remaining blocks
// grid-stride the CSR scatter fill (independent work, overlaps GEMM stalls).
__global__ void __launch_bounds__(256) gemm0_fill_kernel(const float* __restrict__ x,
                                                         const float* __restrict__ W0,
                                                         const int* __restrict__ ei,
                                                         int n, int e, int gemmBlocks) {
    if ((int)blockIdx.x < gemmBlocks) {
        gemm_body<128, false, true>(x, W0, nullptr, nullptr, n, 0, 1.f, blockIdx.x);
    } else {
        int nfb = gridDim.x - gemmBlocks;
        int i = (blockIdx.x - gemmBlocks) * blockDim.x + threadIdx.x;
        int stride = nfb * blockDim.x;
        for (int t = i; t < e; t += stride) {
            int s = ei[t];
            int d = ei[e + t];
            int pos = atomicAdd(&g_cursor[d], 1);
            g_csrsrc[pos] = s;
        }
    }
}

__global__ void __launch_bounds__(256) gemmBN_kernel(const float* __restrict__ W,
                                                     const float* __restrict__ gamma,
                                                     const float* __restrict__ beta,
                                                     int n, int layer, float fn) {
    gemm_body<64, true, false>(nullptr, W, gamma, beta, n, layer, fn, blockIdx.x);
}

// ------------------------- Aggregation: y = dinv*(sum_nbr hs + hs_self) + bias ------------
// 2-stream + unroll-4 (8 outstanding gathers/warp), fp32 hs. Warp per node.
__global__ void __launch_bounds__(256) agg_kernel(const float* __restrict__ bias,
                                                  int n, int layer) {
    int tid = threadIdx.x;
    int gw = (blockIdx.x * blockDim.x + tid) >> 5;
    int nw = (gridDim.x * blockDim.x) >> 5;
    int lane = tid & 31, half = lane >> 4, q = lane & 15;

    const float4* hs4 = (const float4*)g_bufB;
    float4* out4 = (float4*)g_bufA;

    float4 s1 = make_float4(0, 0, 0, 0);
    float4 s2 = make_float4(0, 0, 0, 0);
    float4 b4 = make_float4(bias[q * 4], bias[q * 4 + 1], bias[q * 4 + 2], bias[q * 4 + 3]);

    for (int node = gw; node < n; node += nw) {
        int rs = g_rowptr[node];
        int re = g_rowptr[node + 1];
        float4 acc, aB = make_float4(0, 0, 0, 0);
        float4 aC = make_float4(0, 0, 0, 0), aD = make_float4(0, 0, 0, 0);
        if (half == 0) acc = hs4[(size_t)node * HC + q];   // self-loop term
        else           acc = make_float4(0, 0, 0, 0);

        int e2 = rs + half;
        for (; e2 + 6 < re; e2 += 8) {
            int i1 = g_csrsrc[e2];
            int i2 = g_csrsrc[e2 + 2];
            int i3 = g_csrsrc[e2 + 4];
            int i4 = g_csrsrc[e2 + 6];
            float4 v1 = hs4[(size_t)i1 * HC + q];
            float4 v2 = hs4[(size_t)i2 * HC + q];
            float4 v3 = hs4[(size_t)i3 * HC + q];
            float4 v4 = hs4[(size_t)i4 * HC + q];
            acc.x += v1.x; acc.y += v1.y; acc.z += v1.z; acc.w += v1.w;
            aB.x += v2.x;  aB.y += v2.y;  aB.z += v2.z;  aB.w += v2.w;
            aC.x += v3.x;  aC.y += v3.y;  aC.z += v3.z;  aC.w += v3.w;
            aD.x += v4.x;  aD.y += v4.y;  aD.z += v4.z;  aD.w += v4.w;
        }
        if (e2 + 2 < re) {
            int i1 = g_csrsrc[e2];
            int i2 = g_csrsrc[e2 + 2];
            float4 v1 = hs4[(size_t)i1 * HC + q];
            float4 v2 = hs4[(size_t)i2 * HC + q];
            acc.x += v1.x; acc.y += v1.y; acc.z += v1.z; acc.w += v1.w;
            aB.x += v2.x;  aB.y += v2.y;  aB.z += v2.z;  aB.w += v2.w;
            e2 += 4;
        }
        if (e2 < re) {
            int i1 = g_csrsrc[e2];
            float4 v1 = hs4[(size_t)i1 * HC + q];
            acc.x += v1.x; acc.y += v1.y; acc.z += v1.z; acc.w += v1.w;
        }
        acc.x += aB.x + aC.x + aD.x;
        acc.y += aB.y + aC.y + aD.y;
        acc.z += aB.z + aC.z + aD.z;
        acc.w += aB.w + aC.w + aD.w;

        acc.x += __shfl_xor_sync(0xffffffffu, acc.x, 16);
        acc.y += __shfl_xor_sync(0xffffffffu, acc.y, 16);
        acc.z += __shfl_xor_sync(0xffffffffu, acc.z, 16);
        acc.w += __shfl_xor_sync(0xffffffffu, acc.w, 16);
        if (half == 0) {
            float dv = g_dinv[node];
            float4 y;
            y.x = fmaf(acc.x, dv, b4.x);
            y.y = fmaf(acc.y, dv, b4.y);
            y.z = fmaf(acc.z, dv, b4.z);
            y.w = fmaf(acc.w, dv, b4.w);
            out4[(size_t)node * HC + q] = y;
            s1.x += y.x; s1.y += y.y; s1.z += y.z; s1.w += y.w;
            s2.x += y.x * y.x; s2.y += y.y * y.y; s2.z += y.z * y.z; s2.w += y.w * y.w;
        }
    }

    __shared__ float ssum[H], ssq[H];
    if (tid < H) { ssum[tid] = 0.f; ssq[tid] = 0.f; }
    __syncthreads();
    if (half == 0) {
        int c0 = q * 4;
        atomicAdd(&ssum[c0 + 0], s1.x); atomicAdd(&ssum[c0 + 1], s1.y);
        atomicAdd(&ssum[c0 + 2], s1.z); atomicAdd(&ssum[c0 + 3], s1.w);
        atomicAdd(&ssq[c0 + 0], s2.x);  atomicAdd(&ssq[c0 + 1], s2.y);
        atomicAdd(&ssq[c0 + 2], s2.z);  atomicAdd(&ssq[c0 + 3], s2.w);
    }
    __syncthreads();
    if (tid < H) {
        atomicAdd(&g_sum[layer * H + tid], ssum[tid]);
        atomicAdd(&g_sumsq[layer * H + tid], ssq[tid]);
    }
}

// ------------------------- pooling + MLP (fused, last-block pattern) -----------------------
// 8 blocks per graph (512 blocks). Each block adds its partial (already divided by cnt)
// to g_pool, then bumps a done-counter; the LAST block runs the full 64-graph MLP and
// restores all zero-invariants.
__global__ void __launch_bounds__(256) pool_mlp_kernel(const int* __restrict__ batch,
                                                       const float* __restrict__ gamma,
                                                       const float* __restrict__ beta,
                                                       const float* __restrict__ l1w,
                                                       const float* __restrict__ l1b,
                                                       const float* __restrict__ l2w,
                                                       const float* __restrict__ l2b,
                                                       float* __restrict__ out,
                                                       int n, float fn) {
    __shared__ float sScale[H], sShift[H];
    int tid = threadIdx.x;
    if (tid < H) {
        float m = g_sum[2 * H + tid] / fn;
        float var = g_sumsq[2 * H + tid] / fn - m * m;
        float inv = rsqrtf(var + EPS);
        float sc = inv * gamma[tid];
        sScale[tid] = sc;
        sShift[tid] = beta[tid] - m * sc;
    }
    __syncthreads();

    int g = blockIdx.x >> 3, sub = blockIdx.x & 7;
    int start, end;
    {
        int key = g;
        int lo = 0, hi = n;
        while (lo < hi) { int mid = (lo + hi) >> 1; if (batch[mid] < key) lo = mid + 1; else hi = mid; }
        start = lo;
        key = g + 1;
        lo = 0; hi = n;
        while (lo < hi) { int mid = (lo + hi) >> 1; if (batch[mid] < key) lo = mid + 1; else hi = mid; }
        end = lo;
    }
    int c = tid & 63;
    int rr = tid >> 6;  // 0..3
    float sc = sScale[c], sh = sShift[c];
    float cnt = fmaxf((float)(end - start), 1.f);
    float s = 0.f;
    for (int row = start + sub * 4 + rr; row < end; row += 32)
        s += fmaxf(fmaf(g_bufA[(size_t)row * H + c], sc, sh), 0.f);

    __shared__ float sm[256];
    sm[tid] = s;
    __syncthreads();
    if (tid < 128) sm[tid] += sm[tid + 128];
    __syncthreads();
    if (tid < 64) atomicAdd(&g_pool[g * H + tid], (sm[tid] + sm[tid + 64]) / cnt);

    // last-block MLP
    __shared__ int s_last;
    __threadfence();
    __syncthreads();
    if (tid == 0) {
        int done = atomicAdd(&g_pooldone, 1);
        s_last = (done == (int)gridDim.x - 1) ? 1 : 0;
    }
    __syncthreads();
    if (!s_last) return;

    // this block: 8 warps x 8 graphs each
    int warp = tid >> 5, j = tid & 31;
    for (int gg2 = warp; gg2 < 64; gg2 += 8) {
        float p0 = g_pool[gg2 * H + j];
        float p1 = g_pool[gg2 * H + j + 32];
        float h = l1b[j];
        #pragma unroll
        for (int k = 0; k < 32; k++) {
            float pk = __shfl_sync(0xffffffffu, p0, k);
            h = fmaf(pk, l1w[j * H + k], h);
        }
        #pragma unroll
        for (int k = 0; k < 32; k++) {
            float pk = __shfl_sync(0xffffffffu, p1, k);
            h = fmaf(pk, l1w[j * H + 32 + k], h);
        }
        h = fmaxf(h, 0.f);
        float v = h * l2w[j];
        #pragma unroll
        for (int o = 16; o; o >>= 1) v += __shfl_xor_sync(0xffffffffu, v, o);
        if (j == 0) out[gg2] = v + l2b[0];
    }
    // restore zero invariants for next replay
    __syncthreads();
    for (int t2 = tid; t2 < 64 * H; t2 += 256) g_pool[t2] = 0.f;
    for (int t2 = tid; t2 < 3 * H; t2 += 256) { g_sum[t2] = 0.f; g_sumsq[t2] = 0.f; }
    if (tid == 0) g_pooldone = 0;
}

// ------------------------- host launcher -------------------------
extern "C" void kernel_launch(void* const* d_in, const int* in_sizes, int n_in,
                              void* d_out, int out_size) {
    const float* x     = (const float*)d_in[0];
    const int*   ei    = (const int*)d_in[1];     // int32 on device (JAX x64 disabled)
    const int*   batch = (const int*)d_in[2];
    const float* W0  = (const float*)d_in[3];
    const float* b0  = (const float*)d_in[4];
    const float* gm0 = (const float*)d_in[5];
    const float* be0 = (const float*)d_in[6];
    const float* W1  = (const float*)d_in[7];
    const float* b1  = (const float*)d_in[8];
    const float* gm1 = (const float*)d_in[9];
    const float* be1 = (const float*)d_in[10];
    const float* W2  = (const float*)d_in[11];
    const float* b2  = (const float*)d_in[12];
    const float* gm2 = (const float*)d_in[13];
    const float* be2 = (const float*)d_in[14];
    const float* l1w = (const float*)d_in[15];
    const float* l1b = (const float*)d_in[16];
    const float* l2w = (const float*)d_in[17];
    const float* l2b = (const float*)d_in[18];

    int n = in_sizes[0] / 128;     // nodes
    int e = in_sizes[1] / 2;       // edges
    int G = out_size;              // graphs (64)

    int nb = (n + 1023) / 1024;    // 49
    int gg = (n + 127) / 128;      // gemm blocks (391)
    int fillBlocks = 192;
    float fn = (float)n;

    csr_build_kernel<<<nb, 1024>>>(ei, n, e);                                            // 1
    gemm0_fill_kernel<<<gg + fillBlocks, 256>>>(x, W0, ei, n, e, gg);                    // 2

    agg_kernel<<<1024, 256>>>(b0, n, 0);                                                 // 3
    gemmBN_kernel<<<gg, 256>>>(W1, gm0, be0, n, 0, fn);                                  // 4
    agg_kernel<<<1024, 256>>>(b1, n, 1);                                                 // 5
    gemmBN_kernel<<<gg, 256>>>(W2, gm1, be1, n, 1, fn);                                  // 6
    agg_kernel<<<1024, 256>>>(b2, n, 2);                                                 // 7

    pool_mlp_kernel<<<G * 8, 256>>>(batch, gm2, be2, l1w, l1b, l2w, l2b,
                                    (float*)d_out, n, fn);                               // 8
}